// round 11
// baseline (speedup 1.0000x reference)
#include <cuda_runtime.h>
#include <cuda_bf16.h>
#include <cstdint>

#define NN 20000
#define NE 100000
#define NG 64

// ---------------- device scratch (static; no runtime allocation) -------------
__device__ float g_S1[NN * 260];
__device__ float g_h1[NN * 64];
__device__ float g_R[NN * 64];
__device__ float g_Q[163840000];     // [NN][8192]
__device__ float g_agg2[NN * 64];
__device__ int   g_deg[NN];
__device__ int   g_outdeg[NN];
__device__ int   g_rowstart[NN + 1];
__device__ int   g_cursor[NN];
__device__ int   g_ebysrc[NE];
__device__ float g_pool[NG * 64];
__device__ int   g_gcnt[NG];

__device__ __forceinline__ uint32_t smem_u32(const void* p) {
    uint32_t a;
    asm("{ .reg .u64 t; cvta.to.shared.u64 t, %1; cvt.u32.u64 %0, t; }" : "=r"(a) : "l"(p));
    return a;
}
__device__ __forceinline__ void ldsm_x4(uint32_t& r0, uint32_t& r1, uint32_t& r2, uint32_t& r3,
                                        uint32_t addr) {
    asm volatile("ldmatrix.sync.aligned.m8n8.x4.shared.b16 {%0,%1,%2,%3}, [%4];"
                 : "=r"(r0), "=r"(r1), "=r"(r2), "=r"(r3) : "r"(addr));
}
__device__ __forceinline__ void mma_bf16(float* d, const uint32_t* a, const uint32_t* b) {
    asm volatile(
        "mma.sync.aligned.m16n8k16.row.col.f32.bf16.bf16.f32 "
        "{%0,%1,%2,%3}, {%4,%5,%6,%7}, {%8,%9}, {%0,%1,%2,%3};"
        : "+f"(d[0]), "+f"(d[1]), "+f"(d[2]), "+f"(d[3])
        : "r"(a[0]), "r"(a[1]), "r"(a[2]), "r"(a[3]), "r"(b[0]), "r"(b[1]));
}

// ---------------- kernels ----------------------------------------------------
__global__ void k_zero() {
    int i = blockIdx.x * blockDim.x + threadIdx.x;
    int st = gridDim.x * blockDim.x;
    for (int j = i; j < NN * 260; j += st) g_S1[j] = 0.f;
    for (int j = i; j < NN * 64; j += st) g_agg2[j] = 0.f;
    for (int j = i; j < NG * 64; j += st) g_pool[j] = 0.f;
    for (int j = i; j < NN; j += st) { g_deg[j] = 0; g_outdeg[j] = 0; g_cursor[j] = 0; }
    for (int j = i; j < NG; j += st) g_gcnt[j] = 0;
}

// layer1 edges: z1 = relu(ea@eW1_1+eb1_1); scatter z1 (x) x_src, and x_src; count degs
__global__ void k_l1_edge(const int* __restrict__ ei, const float* __restrict__ ea,
                          const float* __restrict__ x,
                          const float* __restrict__ eW1, const float* __restrict__ eb1) {
    int t = threadIdx.x;                 // 256 = 4 edges x 64
    int k = t & 63;
    int e = blockIdx.x * 4 + (t >> 6);   // 25000*4 = 100000
    int src = ei[e], dst = ei[NE + e];
    float a0 = ea[e * 4 + 0], a1 = ea[e * 4 + 1], a2 = ea[e * 4 + 2], a3 = ea[e * 4 + 3];
    float z = eb1[k] + a0 * eW1[k] + a1 * eW1[64 + k] + a2 * eW1[128 + k] + a3 * eW1[192 + k];
    z = fmaxf(z, 0.f);
    float x0 = x[src * 4 + 0], x1 = x[src * 4 + 1], x2 = x[src * 4 + 2], x3 = x[src * 4 + 3];
    float* S = g_S1 + dst * 260;
    atomicAdd(S + k * 4 + 0, z * x0);
    atomicAdd(S + k * 4 + 1, z * x1);
    atomicAdd(S + k * 4 + 2, z * x2);
    atomicAdd(S + k * 4 + 3, z * x3);
    if (k < 4) atomicAdd(S + 256 + k, x[src * 4 + k]);
    if (k == 0) { atomicAdd(&g_deg[dst], 1); atomicAdd(&g_outdeg[src], 1); }
}

// layer1 node + fused layernorm -> g_h1
__global__ void k_l1_node_ln(const float* __restrict__ eW2, const float* __restrict__ eb2,
                             const float* __restrict__ x, const float* __restrict__ root1,
                             const float* __restrict__ bias1,
                             const float* __restrict__ gam, const float* __restrict__ bet) {
    __shared__ float sS[16 * 260];
    __shared__ float sT[16 * 66];
    int o = threadIdx.x;                 // 64
    int v0 = blockIdx.x * 16;            // 1250*16 = 20000
    for (int l = o; l < 16 * 260; l += 64) sS[l] = g_S1[v0 * 260 + l];
    __syncthreads();
    float acc[16];
    #pragma unroll
    for (int n = 0; n < 16; n++) acc[n] = 0.f;
    for (int k = 0; k < 64; k++) {
        #pragma unroll
        for (int i = 0; i < 4; i++) {
            float w = eW2[k * 256 + i * 64 + o];
            #pragma unroll
            for (int n = 0; n < 16; n++) acc[n] += sS[n * 260 + k * 4 + i] * w;
        }
    }
    #pragma unroll
    for (int i = 0; i < 4; i++) {
        float w = eb2[i * 64 + o];
        #pragma unroll
        for (int n = 0; n < 16; n++) acc[n] += sS[n * 260 + 256 + i] * w;
    }
    for (int n = 0; n < 16; n++) {
        int v = v0 + n;
        float d = fmaxf((float)g_deg[v], 1.f);
        float r = bias1[o];
        #pragma unroll
        for (int i = 0; i < 4; i++) r += x[v * 4 + i] * root1[i * 64 + o];
        sT[n * 66 + o] = fmaxf(acc[n] / d + r, 0.f);
    }
    __syncthreads();
    int lane = o & 31, w = o >> 5;
    float gA = gam[lane], gB = gam[32 + lane];
    float bA = bet[lane], bB = bet[32 + lane];
    for (int j = 0; j < 8; j++) {
        int n = w * 8 + j;
        int v = v0 + n;
        float t0 = sT[n * 66 + lane], t1 = sT[n * 66 + 32 + lane];
        float s = t0 + t1;
        #pragma unroll
        for (int d = 16; d; d >>= 1) s += __shfl_xor_sync(0xffffffffu, s, d);
        float mu = s * (1.f / 64.f);
        float d0 = t0 - mu, d1 = t1 - mu;
        float q = d0 * d0 + d1 * d1;
        #pragma unroll
        for (int d = 16; d; d >>= 1) q += __shfl_xor_sync(0xffffffffu, q, d);
        float rs = rsqrtf(q * (1.f / 64.f) + 1e-5f);
        g_h1[v * 64 + lane]      = d0 * rs * gA + bA;
        g_h1[v * 64 + 32 + lane] = d1 * rs * gB + bB;
    }
}

// ---------------- mma.sync Q-GEMM: Q = h1 [20000x64] @ B [64x8192] ------------
// bf16-split via chunk addressing: sA = [a_hi(64) | a_lo(64)] per row,
// sB = [b_hi(64) | b_lo(64)] per row (n-major). 12 virtual k-steps:
//   s=0..3: ah*bh, s=4..7: al*bh, s=8..11: ah*bl  (fp32 accumulate).
// CTA 128 thr (4 warps), tile M=64 x N=128; warp tile 64m x 32n.
// Row stride 136 elems (272B = 17*16B) -> ldmatrix rows conflict-free.
#define QG_STRIDE 136
#define QG_SMEM ((64 + 128) * QG_STRIDE * 2)    // 52224 B

__global__ void __launch_bounds__(128) k_qgemm_mma(const float* __restrict__ W) {
    extern __shared__ __align__(16) char dsm[];
    __nv_bfloat16* sA = (__nv_bfloat16*)dsm;                        // [64][136]
    __nv_bfloat16* sB = (__nv_bfloat16*)(dsm + 64 * QG_STRIDE * 2); // [128][136]
    int t = threadIdx.x;
    int v0 = blockIdx.x * 64;            // 313 tiles (tail in last)
    int c0 = blockIdx.y * 128;           // 64 tiles

    // ---- A: h1 tile [64 m x 64 k] -> hi/lo chunks ---------------------------
    for (int idx = t; idx < 4096; idx += 128) {
        int m = idx >> 6, k = idx & 63;
        int r = v0 + m;
        float val = (r < NN) ? g_h1[r * 64 + k] : 0.f;
        __nv_bfloat16 hi = __float2bfloat16(val);
        __nv_bfloat16 lo = __float2bfloat16(val - __bfloat162float(hi));
        __nv_bfloat16* row = sA + m * QG_STRIDE;
        row[k] = hi; row[64 + k] = lo;
    }
    // ---- B: cols c0..c0+127; col C=k2*64+o -> W[k2*4096 + i*64 + o], k=i ----
    int k2b = c0 >> 6;
    for (int j = 0; j < 2; j++) {
        const float* Wb = W + (size_t)(k2b + j) * 4096;
        for (int idx = t; idx < 4096; idx += 128) {
            int i = idx >> 6, o = idx & 63;       // coalesced global read
            float val = Wb[idx];
            __nv_bfloat16 hi = __float2bfloat16(val);
            __nv_bfloat16 lo = __float2bfloat16(val - __bfloat162float(hi));
            __nv_bfloat16* row = sB + (j * 64 + o) * QG_STRIDE;
            row[i] = hi; row[64 + i] = lo;
        }
    }
    __syncthreads();

    int warp = t >> 5, lane = t & 31;
    int n0 = warp * 32;                   // warp covers n0..n0+31, all 64 m
    float acc[4][4][4];                   // [fA m16][2*fB+half n8][4]
    #pragma unroll
    for (int fa = 0; fa < 4; fa++)
        #pragma unroll
        for (int fb = 0; fb < 4; fb++)
            #pragma unroll
            for (int u = 0; u < 4; u++) acc[fa][fb][u] = 0.f;

    int l7 = lane & 7;
    uint32_t sAu = smem_u32(sA), sBu = smem_u32(sB);
    uint32_t aRowOff = (uint32_t)(l7 + (((lane >> 3) & 1) << 3));
    uint32_t aColOff = ((lane >> 4) & 1) << 3;
    uint32_t bRowOff = (uint32_t)(l7 + (((lane >> 4) & 1) << 3));
    uint32_t bColOff = ((lane >> 3) & 1) << 3;

    #pragma unroll
    for (int s = 0; s < 12; s++) {
        int aOff = (s & 3) * 16 + ((s >= 4 && s < 8) ? 64 : 0);
        int bOff = (s & 3) * 16 + ((s >= 8) ? 64 : 0);
        uint32_t a[4][4];
        #pragma unroll
        for (int fa = 0; fa < 4; fa++)
            ldsm_x4(a[fa][0], a[fa][1], a[fa][2], a[fa][3],
                    sAu + (((fa * 16) + aRowOff) * QG_STRIDE + aOff + aColOff) * 2);
        #pragma unroll
        for (int fb = 0; fb < 2; fb++) {
            uint32_t b[4];
            ldsm_x4(b[0], b[1], b[2], b[3],
                    sBu + ((n0 + fb * 16 + bRowOff) * QG_STRIDE + bOff + bColOff) * 2);
            #pragma unroll
            for (int fa = 0; fa < 4; fa++) {
                mma_bf16(acc[fa][2 * fb],     a[fa], b);
                mma_bf16(acc[fa][2 * fb + 1], a[fa], b + 2);
            }
        }
    }

    // ---- epilogue: frag (m16n8): d0,d1 -> (row, col..col+1), d2,d3 -> row+8 --
    int mr = lane >> 2;
    int cb = c0 + n0 + 2 * (lane & 3);
    #pragma unroll
    for (int fa = 0; fa < 4; fa++) {
        int r0g = v0 + fa * 16 + mr, r1g = r0g + 8;
        #pragma unroll
        for (int fb = 0; fb < 4; fb++) {
            int c = cb + fb * 8;
            if (r0g < NN) *(float2*)(g_Q + (size_t)r0g * 8192 + c) =
                make_float2(acc[fa][fb][0], acc[fa][fb][1]);
            if (r1g < NN) *(float2*)(g_Q + (size_t)r1g * 8192 + c) =
                make_float2(acc[fa][fb][2], acc[fa][fb][3]);
        }
    }
}

// exclusive scan of outdeg -> rowstart; single block of 1024
__global__ void k_scan() {
    __shared__ int wsum[32];
    __shared__ int carry;
    int t = threadIdx.x, lane = t & 31, wid = t >> 5;
    if (t == 0) carry = 0;
    __syncthreads();
    for (int base = 0; base < NN; base += 1024) {
        int i = base + t;
        int v = (i < NN) ? g_outdeg[i] : 0;
        int incl = v;
        #pragma unroll
        for (int d = 1; d < 32; d <<= 1) {
            int y = __shfl_up_sync(0xffffffffu, incl, d);
            if (lane >= d) incl += y;
        }
        if (lane == 31) wsum[wid] = incl;
        __syncthreads();
        if (wid == 0) {
            int wv = wsum[lane];
            #pragma unroll
            for (int d = 1; d < 32; d <<= 1) {
                int y = __shfl_up_sync(0xffffffffu, wv, d);
                if (lane >= d) wv += y;
            }
            wsum[lane] = wv;
        }
        __syncthreads();
        int pre = ((wid > 0) ? wsum[wid - 1] : 0) + carry;
        if (i < NN) g_rowstart[i] = pre + incl - v;
        __syncthreads();
        if (t == 0) carry += wsum[31];
        __syncthreads();
    }
    if (t == 0) g_rowstart[NN] = carry;
}

__global__ void k_fill(const int* __restrict__ ei) {
    int e = blockIdx.x * blockDim.x + threadIdx.x;
    if (e < NE) {
        int src = ei[e];
        int p = atomicAdd(&g_cursor[src], 1);
        g_ebysrc[g_rowstart[src] + p] = e;
    }
}

// R[v][o] = sum_i h1[v][i] * eb2_2[i*64+o]
__global__ void k_rgemm(const float* __restrict__ eb2) {
    __shared__ float sw[4096];
    int o = threadIdx.x;                 // 64
    for (int j = o; j < 4096; j += 64) sw[j] = eb2[j];
    __syncthreads();
    int v0 = blockIdx.x * 8;             // 2500*8
    for (int n = 0; n < 8; n++) {
        int v = v0 + n;
        float acc = 0.f;
        #pragma unroll 8
        for (int i = 0; i < 64; i++) acc += g_h1[v * 64 + i] * sw[i * 64 + o];
        g_R[v * 64 + o] = acc;
    }
}

// layer2 edge pass: one CTA per src node; Q row in smem; per-edge z2 then msg scatter
__global__ void __launch_bounds__(128) k_l2_edge(const int* __restrict__ ei,
                                                 const float* __restrict__ ea,
                                                 const float* __restrict__ eW1,
                                                 const float* __restrict__ eb1) {
    __shared__ float sQ[8192];
    __shared__ float sR[64];
    __shared__ float sz[128];
    __shared__ float4 sred4[128];
    int v = blockIdx.x;
    int r0 = g_rowstart[v], r1 = g_rowstart[v + 1];
    if (r0 == r1) return;
    int t = threadIdx.x;                 // 128
    const float* Qrow = g_Q + (size_t)v * 8192;
    for (int j = t; j < 2048; j += 128) ((float4*)sQ)[j] = ((const float4*)Qrow)[j];
    if (t < 64) sR[t] = g_R[v * 64 + t];
    float w0 = eW1[t], w1 = eW1[128 + t], w2 = eW1[256 + t], w3 = eW1[384 + t];
    float bz = eb1[t];
    int o4 = (t & 15) * 4, h = t >> 4;
    __syncthreads();
    for (int p = r0; p < r1; p++) {
        int e = g_ebysrc[p];
        int dst = ei[NE + e];
        float a0 = ea[e * 4], a1 = ea[e * 4 + 1], a2 = ea[e * 4 + 2], a3 = ea[e * 4 + 3];
        sz[t] = fmaxf(bz + a0 * w0 + a1 * w1 + a2 * w2 + a3 * w3, 0.f);
        __syncthreads();
        float4 acc = {0, 0, 0, 0};
        int kb = h * 16;
        #pragma unroll
        for (int kk = 0; kk < 16; kk++) {
            float s = sz[kb + kk];
            float4 q = *(const float4*)(sQ + (kb + kk) * 64 + o4);
            acc.x += s * q.x; acc.y += s * q.y; acc.z += s * q.z; acc.w += s * q.w;
        }
        sred4[t] = acc;
        __syncthreads();
        if (t < 16) {
            float4 m = sred4[t];
            #pragma unroll
            for (int hh = 1; hh < 8; hh++) {
                float4 u = sred4[hh * 16 + t];
                m.x += u.x; m.y += u.y; m.z += u.z; m.w += u.w;
            }
            int o = t * 4;
            atomicAdd(&g_agg2[dst * 64 + o],     m.x + sR[o]);
            atomicAdd(&g_agg2[dst * 64 + o + 1], m.y + sR[o + 1]);
            atomicAdd(&g_agg2[dst * 64 + o + 2], m.z + sR[o + 2]);
            atomicAdd(&g_agg2[dst * 64 + o + 3], m.w + sR[o + 3]);
        }
        __syncthreads();
    }
}

// layer2 node + fused LN + pool scatter
__global__ void k_l2_node_ln(const float* __restrict__ root2, const float* __restrict__ bias2,
                             const float* __restrict__ gam, const float* __restrict__ bet,
                             const int* __restrict__ batch) {
    __shared__ float sw[4096];
    __shared__ float sT[8 * 66];
    int o = threadIdx.x;                 // 64
    for (int j = o; j < 4096; j += 64) sw[j] = root2[j];
    __syncthreads();
    int v0 = blockIdx.x * 8;             // 2500*8
    for (int n = 0; n < 8; n++) {
        int v = v0 + n;
        float acc = bias2[o];
        #pragma unroll 8
        for (int i = 0; i < 64; i++) acc += g_h1[v * 64 + i] * sw[i * 64 + o];
        float d = fmaxf((float)g_deg[v], 1.f);
        sT[n * 66 + o] = fmaxf(g_agg2[v * 64 + o] / d + acc, 0.f);
    }
    __syncthreads();
    int lane = o & 31, w = o >> 5;
    float gA = gam[lane], gB = gam[32 + lane];
    float bA = bet[lane], bB = bet[32 + lane];
    for (int j = 0; j < 4; j++) {
        int n = w * 4 + j;
        int v = v0 + n;
        float t0 = sT[n * 66 + lane], t1 = sT[n * 66 + 32 + lane];
        float s = t0 + t1;
        #pragma unroll
        for (int d = 16; d; d >>= 1) s += __shfl_xor_sync(0xffffffffu, s, d);
        float mu = s * (1.f / 64.f);
        float d0 = t0 - mu, d1 = t1 - mu;
        float q = d0 * d0 + d1 * d1;
        #pragma unroll
        for (int d = 16; d; d >>= 1) q += __shfl_xor_sync(0xffffffffu, q, d);
        float rs = rsqrtf(q * (1.f / 64.f) + 1e-5f);
        float y0 = d0 * rs * gA + bA;
        float y1 = d1 * rs * gB + bB;
        int b = batch[v];
        atomicAdd(&g_pool[b * 64 + lane], y0);
        atomicAdd(&g_pool[b * 64 + 32 + lane], y1);
        if (lane == 0) atomicAdd(&g_gcnt[b], 1);
    }
}

__global__ void k_out(float* __restrict__ out) {
    int i = blockIdx.x * blockDim.x + threadIdx.x;
    if (i < NG * 64) {
        float c = fmaxf((float)g_gcnt[i >> 6], 1.f);
        out[i] = g_pool[i] / c;
    }
}

// ---------------- launch ------------------------------------------------------
extern "C" void kernel_launch(void* const* d_in, const int* in_sizes, int n_in,
                              void* d_out, int out_size) {
    const float* x      = (const float*)d_in[0];
    const int*   ei     = (const int*)  d_in[1];
    const float* ea     = (const float*)d_in[2];
    const int*   batch  = (const int*)  d_in[3];
    const float* eW1_1  = (const float*)d_in[4];
    const float* eb1_1  = (const float*)d_in[5];
    const float* eW2_1  = (const float*)d_in[6];
    const float* eb2_1  = (const float*)d_in[7];
    const float* root1  = (const float*)d_in[8];
    const float* bias1  = (const float*)d_in[9];
    const float* g1     = (const float*)d_in[10];
    const float* b1     = (const float*)d_in[11];
    const float* eW1_2  = (const float*)d_in[12];
    const float* eb1_2  = (const float*)d_in[13];
    const float* eW2_2  = (const float*)d_in[14];
    const float* eb2_2  = (const float*)d_in[15];
    const float* root2  = (const float*)d_in[16];
    const float* bias2  = (const float*)d_in[17];
    const float* g2     = (const float*)d_in[18];
    const float* b2     = (const float*)d_in[19];
    float* out = (float*)d_out;

    cudaFuncSetAttribute(k_qgemm_mma, cudaFuncAttributeMaxDynamicSharedMemorySize, QG_SMEM);

    k_zero<<<2048, 256>>>();                                               // 0
    k_l1_edge<<<NE / 4, 256>>>(ei, ea, x, eW1_1, eb1_1);                   // 1
    k_l1_node_ln<<<NN / 16, 64>>>(eW2_1, eb2_1, x, root1, bias1, g1, b1);  // 2
    k_qgemm_mma<<<dim3(313, 64), 128, QG_SMEM>>>(eW2_2);                   // 3 <- ncu window
    k_scan<<<1, 1024>>>();                                                 // 4
    k_fill<<<(NE + 255) / 256, 256>>>(ei);                                 // 5
    k_rgemm<<<NN / 8, 64>>>(eb2_2);                                        // 6
    k_l2_edge<<<NN, 128>>>(ei, ea, eW1_2, eb1_2);                          // 7
    k_l2_node_ln<<<NN / 8, 64>>>(root2, bias2, g2, b2, batch);             // 8
    k_out<<<(NG * 64 + 255) / 256, 256>>>(out);                            // 9
}

// round 13
// speedup vs baseline: 1.2752x; 1.2752x over previous
#include <cuda_runtime.h>
#include <cuda_bf16.h>
#include <cstdint>

#define NN 20000
#define NE 100000
#define NG 64

// ---------------- device scratch (static; no runtime allocation) -------------
__device__ float g_S1[NN * 260];
__device__ float g_h1[NN * 64];
__device__ float g_R[NN * 64];
__device__ float g_Q[163840000];     // [NN][8192]
__device__ float g_agg2[NN * 64];
__device__ int   g_deg[NN];
__device__ int   g_outdeg[NN];
__device__ int   g_rowstart[NN + 1];
__device__ int   g_cursor[NN];
__device__ int   g_ebysrc[NE];
__device__ float g_pool[NG * 64];
__device__ int   g_gcnt[NG];

__device__ __forceinline__ uint32_t smem_u32(const void* p) {
    uint32_t a;
    asm("{ .reg .u64 t; cvta.to.shared.u64 t, %1; cvt.u32.u64 %0, t; }" : "=r"(a) : "l"(p));
    return a;
}
__device__ __forceinline__ void ldsm_x4(uint32_t& r0, uint32_t& r1, uint32_t& r2, uint32_t& r3,
                                        uint32_t addr) {
    asm volatile("ldmatrix.sync.aligned.m8n8.x4.shared.b16 {%0,%1,%2,%3}, [%4];"
                 : "=r"(r0), "=r"(r1), "=r"(r2), "=r"(r3) : "r"(addr));
}
__device__ __forceinline__ void mma_bf16(float* d, const uint32_t* a, const uint32_t* b) {
    asm volatile(
        "mma.sync.aligned.m16n8k16.row.col.f32.bf16.bf16.f32 "
        "{%0,%1,%2,%3}, {%4,%5,%6,%7}, {%8,%9}, {%0,%1,%2,%3};"
        : "+f"(d[0]), "+f"(d[1]), "+f"(d[2]), "+f"(d[3])
        : "r"(a[0]), "r"(a[1]), "r"(a[2]), "r"(a[3]), "r"(b[0]), "r"(b[1]));
}

// ---------------- kernels ----------------------------------------------------
__global__ void k_zero() {
    int i = blockIdx.x * blockDim.x + threadIdx.x;
    int st = gridDim.x * blockDim.x;
    for (int j = i; j < NN * 260; j += st) g_S1[j] = 0.f;
    for (int j = i; j < NN * 64; j += st) g_agg2[j] = 0.f;
    for (int j = i; j < NG * 64; j += st) g_pool[j] = 0.f;
    for (int j = i; j < NN; j += st) { g_deg[j] = 0; g_outdeg[j] = 0; g_cursor[j] = 0; }
    for (int j = i; j < NG; j += st) g_gcnt[j] = 0;
}

// layer1 edges: z1 = relu(ea@eW1_1+eb1_1); scatter z1 (x) x_src, and x_src; count degs
__global__ void k_l1_edge(const int* __restrict__ ei, const float* __restrict__ ea,
                          const float* __restrict__ x,
                          const float* __restrict__ eW1, const float* __restrict__ eb1) {
    int t = threadIdx.x;                 // 256 = 4 edges x 64
    int k = t & 63;
    int e = blockIdx.x * 4 + (t >> 6);   // 25000*4 = 100000
    int src = ei[e], dst = ei[NE + e];
    float a0 = ea[e * 4 + 0], a1 = ea[e * 4 + 1], a2 = ea[e * 4 + 2], a3 = ea[e * 4 + 3];
    float z = eb1[k] + a0 * eW1[k] + a1 * eW1[64 + k] + a2 * eW1[128 + k] + a3 * eW1[192 + k];
    z = fmaxf(z, 0.f);
    float x0 = x[src * 4 + 0], x1 = x[src * 4 + 1], x2 = x[src * 4 + 2], x3 = x[src * 4 + 3];
    float* S = g_S1 + dst * 260;
    atomicAdd(S + k * 4 + 0, z * x0);
    atomicAdd(S + k * 4 + 1, z * x1);
    atomicAdd(S + k * 4 + 2, z * x2);
    atomicAdd(S + k * 4 + 3, z * x3);
    if (k < 4) atomicAdd(S + 256 + k, x[src * 4 + k]);
    if (k == 0) { atomicAdd(&g_deg[dst], 1); atomicAdd(&g_outdeg[src], 1); }
}

// layer1 node + fused layernorm -> g_h1
__global__ void k_l1_node_ln(const float* __restrict__ eW2, const float* __restrict__ eb2,
                             const float* __restrict__ x, const float* __restrict__ root1,
                             const float* __restrict__ bias1,
                             const float* __restrict__ gam, const float* __restrict__ bet) {
    __shared__ float sS[16 * 260];
    __shared__ float sT[16 * 66];
    int o = threadIdx.x;                 // 64
    int v0 = blockIdx.x * 16;            // 1250*16 = 20000
    for (int l = o; l < 16 * 260; l += 64) sS[l] = g_S1[v0 * 260 + l];
    __syncthreads();
    float acc[16];
    #pragma unroll
    for (int n = 0; n < 16; n++) acc[n] = 0.f;
    for (int k = 0; k < 64; k++) {
        #pragma unroll
        for (int i = 0; i < 4; i++) {
            float w = eW2[k * 256 + i * 64 + o];
            #pragma unroll
            for (int n = 0; n < 16; n++) acc[n] += sS[n * 260 + k * 4 + i] * w;
        }
    }
    #pragma unroll
    for (int i = 0; i < 4; i++) {
        float w = eb2[i * 64 + o];
        #pragma unroll
        for (int n = 0; n < 16; n++) acc[n] += sS[n * 260 + 256 + i] * w;
    }
    for (int n = 0; n < 16; n++) {
        int v = v0 + n;
        float d = fmaxf((float)g_deg[v], 1.f);
        float r = bias1[o];
        #pragma unroll
        for (int i = 0; i < 4; i++) r += x[v * 4 + i] * root1[i * 64 + o];
        sT[n * 66 + o] = fmaxf(acc[n] / d + r, 0.f);
    }
    __syncthreads();
    int lane = o & 31, w = o >> 5;
    float gA = gam[lane], gB = gam[32 + lane];
    float bA = bet[lane], bB = bet[32 + lane];
    for (int j = 0; j < 8; j++) {
        int n = w * 8 + j;
        int v = v0 + n;
        float t0 = sT[n * 66 + lane], t1 = sT[n * 66 + 32 + lane];
        float s = t0 + t1;
        #pragma unroll
        for (int d = 16; d; d >>= 1) s += __shfl_xor_sync(0xffffffffu, s, d);
        float mu = s * (1.f / 64.f);
        float d0 = t0 - mu, d1 = t1 - mu;
        float q = d0 * d0 + d1 * d1;
        #pragma unroll
        for (int d = 16; d; d >>= 1) q += __shfl_xor_sync(0xffffffffu, q, d);
        float rs = rsqrtf(q * (1.f / 64.f) + 1e-5f);
        g_h1[v * 64 + lane]      = d0 * rs * gA + bA;
        g_h1[v * 64 + 32 + lane] = d1 * rs * gB + bB;
    }
}

// ---------------- mma.sync Q-GEMM: Q = h1 [20000x64] @ B [64x8192] ------------
// bf16-split via chunk addressing: sA = [a_hi(64) | a_lo(64)] per row,
// sB = [b_hi(64) | b_lo(64)] per row (n-major). 12 virtual k-steps:
//   s=0..3: ah*bh, s=4..7: al*bh, s=8..11: ah*bl  (fp32 accumulate).
// CTA 128 thr (4 warps), tile M=64 x N=128; warp tile 32m x 64n (2x2 grid).
// Register budget: 64 acc + 8 A + 4 B; __launch_bounds__(128,4) caps at 128 regs
// -> 4 CTAs/SM (smem 52224B x 4 = 209KB <= 228KB).
#define QG_STRIDE 136
#define QG_SMEM ((64 + 128) * QG_STRIDE * 2)    // 52224 B

__global__ void __launch_bounds__(128, 4) k_qgemm_mma(const float* __restrict__ W) {
    extern __shared__ __align__(16) char dsm[];
    __nv_bfloat16* sA = (__nv_bfloat16*)dsm;                        // [64][136]
    __nv_bfloat16* sB = (__nv_bfloat16*)(dsm + 64 * QG_STRIDE * 2); // [128][136]
    int t = threadIdx.x;
    int v0 = blockIdx.x * 64;            // 313 tiles (tail in last)
    int c0 = blockIdx.y * 128;           // 64 tiles

    // ---- A: h1 tile [64 m x 64 k] -> hi/lo chunks ---------------------------
    for (int idx = t; idx < 4096; idx += 128) {
        int m = idx >> 6, k = idx & 63;
        int r = v0 + m;
        float val = (r < NN) ? g_h1[r * 64 + k] : 0.f;
        __nv_bfloat16 hi = __float2bfloat16(val);
        __nv_bfloat16 lo = __float2bfloat16(val - __bfloat162float(hi));
        __nv_bfloat16* row = sA + m * QG_STRIDE;
        row[k] = hi; row[64 + k] = lo;
    }
    // ---- B: cols c0..c0+127; col C=k2*64+o -> W[k2*4096 + i*64 + o], k=i ----
    int k2b = c0 >> 6;
    for (int j = 0; j < 2; j++) {
        const float* Wb = W + (size_t)(k2b + j) * 4096;
        for (int idx = t; idx < 4096; idx += 128) {
            int i = idx >> 6, o = idx & 63;       // coalesced global read
            float val = Wb[idx];
            __nv_bfloat16 hi = __float2bfloat16(val);
            __nv_bfloat16 lo = __float2bfloat16(val - __bfloat162float(hi));
            __nv_bfloat16* row = sB + (j * 64 + o) * QG_STRIDE;
            row[i] = hi; row[64 + i] = lo;
        }
    }
    __syncthreads();

    int warp = t >> 5, lane = t & 31;
    int m0 = (warp & 1) * 32;            // warp tile: 32m x 64n
    int n0 = (warp >> 1) * 64;
    float acc[2][8][4];                  // [fa m16][fb n8][4]
    #pragma unroll
    for (int fa = 0; fa < 2; fa++)
        #pragma unroll
        for (int fb = 0; fb < 8; fb++)
            #pragma unroll
            for (int u = 0; u < 4; u++) acc[fa][fb][u] = 0.f;

    int l7 = lane & 7;
    uint32_t sAu = smem_u32(sA), sBu = smem_u32(sB);
    uint32_t aRowOff = (uint32_t)(m0 + l7 + (((lane >> 3) & 1) << 3));
    uint32_t aColOff = ((lane >> 4) & 1) << 3;
    uint32_t bRowOff = (uint32_t)(n0 + l7 + (((lane >> 4) & 1) << 3));
    uint32_t bColOff = ((lane >> 3) & 1) << 3;

    #pragma unroll 4
    for (int s = 0; s < 12; s++) {
        int aOff = (s & 3) * 16 + ((s >= 4 && s < 8) ? 64 : 0);
        int bOff = (s & 3) * 16 + ((s >= 8) ? 64 : 0);
        uint32_t a[2][4];
        #pragma unroll
        for (int fa = 0; fa < 2; fa++)
            ldsm_x4(a[fa][0], a[fa][1], a[fa][2], a[fa][3],
                    sAu + ((fa * 16 + aRowOff) * QG_STRIDE + aOff + aColOff) * 2);
        #pragma unroll
        for (int nb = 0; nb < 4; nb++) {         // n16 blocks within warp's 64n
            uint32_t b[4];
            ldsm_x4(b[0], b[1], b[2], b[3],
                    sBu + ((nb * 16 + bRowOff) * QG_STRIDE + bOff + bColOff) * 2);
            #pragma unroll
            for (int fa = 0; fa < 2; fa++) {
                mma_bf16(acc[fa][2 * nb],     a[fa], b);
                mma_bf16(acc[fa][2 * nb + 1], a[fa], b + 2);
            }
        }
    }

    // ---- epilogue: frag (m16n8): d0,d1 -> (row, col..col+1), d2,d3 -> row+8 --
    int mr = lane >> 2;
    int cb = c0 + n0 + 2 * (lane & 3);
    #pragma unroll
    for (int fa = 0; fa < 2; fa++) {
        int r0g = v0 + m0 + fa * 16 + mr, r1g = r0g + 8;
        #pragma unroll
        for (int fb = 0; fb < 8; fb++) {
            int c = cb + fb * 8;
            if (r0g < NN) *(float2*)(g_Q + (size_t)r0g * 8192 + c) =
                make_float2(acc[fa][fb][0], acc[fa][fb][1]);
            if (r1g < NN) *(float2*)(g_Q + (size_t)r1g * 8192 + c) =
                make_float2(acc[fa][fb][2], acc[fa][fb][3]);
        }
    }
}

// exclusive scan of outdeg -> rowstart; single block of 1024
__global__ void k_scan() {
    __shared__ int wsum[32];
    __shared__ int carry;
    int t = threadIdx.x, lane = t & 31, wid = t >> 5;
    if (t == 0) carry = 0;
    __syncthreads();
    for (int base = 0; base < NN; base += 1024) {
        int i = base + t;
        int v = (i < NN) ? g_outdeg[i] : 0;
        int incl = v;
        #pragma unroll
        for (int d = 1; d < 32; d <<= 1) {
            int y = __shfl_up_sync(0xffffffffu, incl, d);
            if (lane >= d) incl += y;
        }
        if (lane == 31) wsum[wid] = incl;
        __syncthreads();
        if (wid == 0) {
            int wv = wsum[lane];
            #pragma unroll
            for (int d = 1; d < 32; d <<= 1) {
                int y = __shfl_up_sync(0xffffffffu, wv, d);
                if (lane >= d) wv += y;
            }
            wsum[lane] = wv;
        }
        __syncthreads();
        int pre = ((wid > 0) ? wsum[wid - 1] : 0) + carry;
        if (i < NN) g_rowstart[i] = pre + incl - v;
        __syncthreads();
        if (t == 0) carry += wsum[31];
        __syncthreads();
    }
    if (t == 0) g_rowstart[NN] = carry;
}

__global__ void k_fill(const int* __restrict__ ei) {
    int e = blockIdx.x * blockDim.x + threadIdx.x;
    if (e < NE) {
        int src = ei[e];
        int p = atomicAdd(&g_cursor[src], 1);
        g_ebysrc[g_rowstart[src] + p] = e;
    }
}

// R[v][o] = sum_i h1[v][i] * eb2_2[i*64+o]
__global__ void k_rgemm(const float* __restrict__ eb2) {
    __shared__ float sw[4096];
    int o = threadIdx.x;                 // 64
    for (int j = o; j < 4096; j += 64) sw[j] = eb2[j];
    __syncthreads();
    int v0 = blockIdx.x * 8;             // 2500*8
    for (int n = 0; n < 8; n++) {
        int v = v0 + n;
        float acc = 0.f;
        #pragma unroll 8
        for (int i = 0; i < 64; i++) acc += g_h1[v * 64 + i] * sw[i * 64 + o];
        g_R[v * 64 + o] = acc;
    }
}

// layer2 edge pass: one CTA per src node; Q row in smem; per-edge z2 then msg scatter
__global__ void __launch_bounds__(128) k_l2_edge(const int* __restrict__ ei,
                                                 const float* __restrict__ ea,
                                                 const float* __restrict__ eW1,
                                                 const float* __restrict__ eb1) {
    __shared__ float sQ[8192];
    __shared__ float sR[64];
    __shared__ float sz[128];
    __shared__ float4 sred4[128];
    int v = blockIdx.x;
    int r0 = g_rowstart[v], r1 = g_rowstart[v + 1];
    if (r0 == r1) return;
    int t = threadIdx.x;                 // 128
    const float* Qrow = g_Q + (size_t)v * 8192;
    for (int j = t; j < 2048; j += 128) ((float4*)sQ)[j] = ((const float4*)Qrow)[j];
    if (t < 64) sR[t] = g_R[v * 64 + t];
    float w0 = eW1[t], w1 = eW1[128 + t], w2 = eW1[256 + t], w3 = eW1[384 + t];
    float bz = eb1[t];
    int o4 = (t & 15) * 4, h = t >> 4;
    __syncthreads();
    for (int p = r0; p < r1; p++) {
        int e = g_ebysrc[p];
        int dst = ei[NE + e];
        float a0 = ea[e * 4], a1 = ea[e * 4 + 1], a2 = ea[e * 4 + 2], a3 = ea[e * 4 + 3];
        sz[t] = fmaxf(bz + a0 * w0 + a1 * w1 + a2 * w2 + a3 * w3, 0.f);
        __syncthreads();
        float4 acc = {0, 0, 0, 0};
        int kb = h * 16;
        #pragma unroll
        for (int kk = 0; kk < 16; kk++) {
            float s = sz[kb + kk];
            float4 q = *(const float4*)(sQ + (kb + kk) * 64 + o4);
            acc.x += s * q.x; acc.y += s * q.y; acc.z += s * q.z; acc.w += s * q.w;
        }
        sred4[t] = acc;
        __syncthreads();
        if (t < 16) {
            float4 m = sred4[t];
            #pragma unroll
            for (int hh = 1; hh < 8; hh++) {
                float4 u = sred4[hh * 16 + t];
                m.x += u.x; m.y += u.y; m.z += u.z; m.w += u.w;
            }
            int o = t * 4;
            atomicAdd(&g_agg2[dst * 64 + o],     m.x + sR[o]);
            atomicAdd(&g_agg2[dst * 64 + o + 1], m.y + sR[o + 1]);
            atomicAdd(&g_agg2[dst * 64 + o + 2], m.z + sR[o + 2]);
            atomicAdd(&g_agg2[dst * 64 + o + 3], m.w + sR[o + 3]);
        }
        __syncthreads();
    }
}

// layer2 node + fused LN + pool scatter
__global__ void k_l2_node_ln(const float* __restrict__ root2, const float* __restrict__ bias2,
                             const float* __restrict__ gam, const float* __restrict__ bet,
                             const int* __restrict__ batch) {
    __shared__ float sw[4096];
    __shared__ float sT[8 * 66];
    int o = threadIdx.x;                 // 64
    for (int j = o; j < 4096; j += 64) sw[j] = root2[j];
    __syncthreads();
    int v0 = blockIdx.x * 8;             // 2500*8
    for (int n = 0; n < 8; n++) {
        int v = v0 + n;
        float acc = bias2[o];
        #pragma unroll 8
        for (int i = 0; i < 64; i++) acc += g_h1[v * 64 + i] * sw[i * 64 + o];
        float d = fmaxf((float)g_deg[v], 1.f);
        sT[n * 66 + o] = fmaxf(g_agg2[v * 64 + o] / d + acc, 0.f);
    }
    __syncthreads();
    int lane = o & 31, w = o >> 5;
    float gA = gam[lane], gB = gam[32 + lane];
    float bA = bet[lane], bB = bet[32 + lane];
    for (int j = 0; j < 4; j++) {
        int n = w * 4 + j;
        int v = v0 + n;
        float t0 = sT[n * 66 + lane], t1 = sT[n * 66 + 32 + lane];
        float s = t0 + t1;
        #pragma unroll
        for (int d = 16; d; d >>= 1) s += __shfl_xor_sync(0xffffffffu, s, d);
        float mu = s * (1.f / 64.f);
        float d0 = t0 - mu, d1 = t1 - mu;
        float q = d0 * d0 + d1 * d1;
        #pragma unroll
        for (int d = 16; d; d >>= 1) q += __shfl_xor_sync(0xffffffffu, q, d);
        float rs = rsqrtf(q * (1.f / 64.f) + 1e-5f);
        float y0 = d0 * rs * gA + bA;
        float y1 = d1 * rs * gB + bB;
        int b = batch[v];
        atomicAdd(&g_pool[b * 64 + lane], y0);
        atomicAdd(&g_pool[b * 64 + 32 + lane], y1);
        if (lane == 0) atomicAdd(&g_gcnt[b], 1);
    }
}

__global__ void k_out(float* __restrict__ out) {
    int i = blockIdx.x * blockDim.x + threadIdx.x;
    if (i < NG * 64) {
        float c = fmaxf((float)g_gcnt[i >> 6], 1.f);
        out[i] = g_pool[i] / c;
    }
}

// ---------------- launch ------------------------------------------------------
extern "C" void kernel_launch(void* const* d_in, const int* in_sizes, int n_in,
                              void* d_out, int out_size) {
    const float* x      = (const float*)d_in[0];
    const int*   ei     = (const int*)  d_in[1];
    const float* ea     = (const float*)d_in[2];
    const int*   batch  = (const int*)  d_in[3];
    const float* eW1_1  = (const float*)d_in[4];
    const float* eb1_1  = (const float*)d_in[5];
    const float* eW2_1  = (const float*)d_in[6];
    const float* eb2_1  = (const float*)d_in[7];
    const float* root1  = (const float*)d_in[8];
    const float* bias1  = (const float*)d_in[9];
    const float* g1     = (const float*)d_in[10];
    const float* b1     = (const float*)d_in[11];
    const float* eW1_2  = (const float*)d_in[12];
    const float* eb1_2  = (const float*)d_in[13];
    const float* eW2_2  = (const float*)d_in[14];
    const float* eb2_2  = (const float*)d_in[15];
    const float* root2  = (const float*)d_in[16];
    const float* bias2  = (const float*)d_in[17];
    const float* g2     = (const float*)d_in[18];
    const float* b2     = (const float*)d_in[19];
    float* out = (float*)d_out;

    cudaFuncSetAttribute(k_qgemm_mma, cudaFuncAttributeMaxDynamicSharedMemorySize, QG_SMEM);

    k_zero<<<2048, 256>>>();                                               // 0
    k_l1_edge<<<NE / 4, 256>>>(ei, ea, x, eW1_1, eb1_1);                   // 1
    k_l1_node_ln<<<NN / 16, 64>>>(eW2_1, eb2_1, x, root1, bias1, g1, b1);  // 2
    k_qgemm_mma<<<dim3(313, 64), 128, QG_SMEM>>>(eW2_2);                   // 3 <- ncu window
    k_scan<<<1, 1024>>>();                                                 // 4
    k_fill<<<(NE + 255) / 256, 256>>>(ei);                                 // 5
    k_rgemm<<<NN / 8, 64>>>(eb2_2);                                        // 6
    k_l2_edge<<<NN, 128>>>(ei, ea, eW1_2, eb1_2);                          // 7
    k_l2_node_ln<<<NN / 8, 64>>>(root2, bias2, g2, b2, batch);             // 8
    k_out<<<(NG * 64 + 255) / 256, 256>>>(out);                            // 9
}

// round 14
// speedup vs baseline: 1.5759x; 1.2358x over previous
#include <cuda_runtime.h>
#include <cuda_bf16.h>
#include <cstdint>

#define NN 20000
#define NE 100000
#define NG 64

// ---------------- device scratch (static; no runtime allocation) -------------
__device__ float g_S1[NN * 260];
__device__ float g_h1[NN * 64];
__device__ float g_R[NN * 64];
__device__ float g_Q[163840000];     // [NN][8192]
__device__ float g_agg2[NN * 64];
__device__ int   g_deg[NN];
__device__ int   g_outdeg[NN];
__device__ int   g_rowstart[NN + 1];
__device__ int   g_cursor[NN];
__device__ int   g_ebysrc[NE];
__device__ float g_pool[NG * 64];
__device__ int   g_gcnt[NG];

__device__ __forceinline__ uint32_t smem_u32(const void* p) {
    uint32_t a;
    asm("{ .reg .u64 t; cvta.to.shared.u64 t, %1; cvt.u32.u64 %0, t; }" : "=r"(a) : "l"(p));
    return a;
}
__device__ __forceinline__ void ldsm_x4(uint32_t& r0, uint32_t& r1, uint32_t& r2, uint32_t& r3,
                                        uint32_t addr) {
    asm volatile("ldmatrix.sync.aligned.m8n8.x4.shared.b16 {%0,%1,%2,%3}, [%4];"
                 : "=r"(r0), "=r"(r1), "=r"(r2), "=r"(r3) : "r"(addr));
}
__device__ __forceinline__ void mma_bf16(float* d, const uint32_t* a, const uint32_t* b) {
    asm volatile(
        "mma.sync.aligned.m16n8k16.row.col.f32.bf16.bf16.f32 "
        "{%0,%1,%2,%3}, {%4,%5,%6,%7}, {%8,%9}, {%0,%1,%2,%3};"
        : "+f"(d[0]), "+f"(d[1]), "+f"(d[2]), "+f"(d[3])
        : "r"(a[0]), "r"(a[1]), "r"(a[2]), "r"(a[3]), "r"(b[0]), "r"(b[1]));
}
__device__ __forceinline__ uint32_t pack_bf16(__nv_bfloat16 a, __nv_bfloat16 b) {
    __nv_bfloat162 p(a, b);
    return *reinterpret_cast<uint32_t*>(&p);
}

// ---------------- kernels ----------------------------------------------------
__global__ void k_zero() {
    int i = blockIdx.x * blockDim.x + threadIdx.x;
    int st = gridDim.x * blockDim.x;
    for (int j = i; j < NN * 260; j += st) g_S1[j] = 0.f;
    for (int j = i; j < NN * 64; j += st) g_agg2[j] = 0.f;
    for (int j = i; j < NG * 64; j += st) g_pool[j] = 0.f;
    for (int j = i; j < NN; j += st) { g_deg[j] = 0; g_outdeg[j] = 0; g_cursor[j] = 0; }
    for (int j = i; j < NG; j += st) g_gcnt[j] = 0;
}

// layer1 edges: z1 = relu(ea@eW1_1+eb1_1); scatter z1 (x) x_src, and x_src; count degs
__global__ void k_l1_edge(const int* __restrict__ ei, const float* __restrict__ ea,
                          const float* __restrict__ x,
                          const float* __restrict__ eW1, const float* __restrict__ eb1) {
    int t = threadIdx.x;                 // 256 = 4 edges x 64
    int k = t & 63;
    int e = blockIdx.x * 4 + (t >> 6);   // 25000*4 = 100000
    int src = ei[e], dst = ei[NE + e];
    float a0 = ea[e * 4 + 0], a1 = ea[e * 4 + 1], a2 = ea[e * 4 + 2], a3 = ea[e * 4 + 3];
    float z = eb1[k] + a0 * eW1[k] + a1 * eW1[64 + k] + a2 * eW1[128 + k] + a3 * eW1[192 + k];
    z = fmaxf(z, 0.f);
    float x0 = x[src * 4 + 0], x1 = x[src * 4 + 1], x2 = x[src * 4 + 2], x3 = x[src * 4 + 3];
    float* S = g_S1 + dst * 260;
    atomicAdd(S + k * 4 + 0, z * x0);
    atomicAdd(S + k * 4 + 1, z * x1);
    atomicAdd(S + k * 4 + 2, z * x2);
    atomicAdd(S + k * 4 + 3, z * x3);
    if (k < 4) atomicAdd(S + 256 + k, x[src * 4 + k]);
    if (k == 0) { atomicAdd(&g_deg[dst], 1); atomicAdd(&g_outdeg[src], 1); }
}

// layer1 node + fused layernorm -> g_h1
__global__ void k_l1_node_ln(const float* __restrict__ eW2, const float* __restrict__ eb2,
                             const float* __restrict__ x, const float* __restrict__ root1,
                             const float* __restrict__ bias1,
                             const float* __restrict__ gam, const float* __restrict__ bet) {
    __shared__ float sS[16 * 260];
    __shared__ float sT[16 * 66];
    int o = threadIdx.x;                 // 64
    int v0 = blockIdx.x * 16;            // 1250*16 = 20000
    for (int l = o; l < 16 * 260; l += 64) sS[l] = g_S1[v0 * 260 + l];
    __syncthreads();
    float acc[16];
    #pragma unroll
    for (int n = 0; n < 16; n++) acc[n] = 0.f;
    for (int k = 0; k < 64; k++) {
        #pragma unroll
        for (int i = 0; i < 4; i++) {
            float w = eW2[k * 256 + i * 64 + o];
            #pragma unroll
            for (int n = 0; n < 16; n++) acc[n] += sS[n * 260 + k * 4 + i] * w;
        }
    }
    #pragma unroll
    for (int i = 0; i < 4; i++) {
        float w = eb2[i * 64 + o];
        #pragma unroll
        for (int n = 0; n < 16; n++) acc[n] += sS[n * 260 + 256 + i] * w;
    }
    for (int n = 0; n < 16; n++) {
        int v = v0 + n;
        float d = fmaxf((float)g_deg[v], 1.f);
        float r = bias1[o];
        #pragma unroll
        for (int i = 0; i < 4; i++) r += x[v * 4 + i] * root1[i * 64 + o];
        sT[n * 66 + o] = fmaxf(acc[n] / d + r, 0.f);
    }
    __syncthreads();
    int lane = o & 31, w = o >> 5;
    float gA = gam[lane], gB = gam[32 + lane];
    float bA = bet[lane], bB = bet[32 + lane];
    for (int j = 0; j < 8; j++) {
        int n = w * 8 + j;
        int v = v0 + n;
        float t0 = sT[n * 66 + lane], t1 = sT[n * 66 + 32 + lane];
        float s = t0 + t1;
        #pragma unroll
        for (int d = 16; d; d >>= 1) s += __shfl_xor_sync(0xffffffffu, s, d);
        float mu = s * (1.f / 64.f);
        float d0 = t0 - mu, d1 = t1 - mu;
        float q = d0 * d0 + d1 * d1;
        #pragma unroll
        for (int d = 16; d; d >>= 1) q += __shfl_xor_sync(0xffffffffu, q, d);
        float rs = rsqrtf(q * (1.f / 64.f) + 1e-5f);
        g_h1[v * 64 + lane]      = d0 * rs * gA + bA;
        g_h1[v * 64 + 32 + lane] = d1 * rs * gB + bB;
    }
}

// ---------------- mma.sync Q-GEMM: Q = h1 [20000x64] @ B [64x8192] ------------
// bf16-split via chunk addressing: sA = [a_hi(64) | a_lo(64)] per row,
// sB = [b_hi(64) | b_lo(64)] per row (n-major). 12 virtual k-steps:
//   s=0..3: ah*bh, s=4..7: al*bh, s=8..11: ah*bl  (fp32 accumulate).
// CTA 128 thr (4 warps), tile M=64 x N=128; warp tile 32m x 64n (2x2 grid).
// Prologue vectorized: A via LDG.128 + STS.64 pairs; B via coalesced LDG.32 x4
// (consecutive-i) + STS.64 pairs.
#define QG_STRIDE 136
#define QG_SMEM ((64 + 128) * QG_STRIDE * 2)    // 52224 B

__global__ void __launch_bounds__(128, 4) k_qgemm_mma(const float* __restrict__ W) {
    extern __shared__ __align__(16) char dsm[];
    __nv_bfloat16* sA = (__nv_bfloat16*)dsm;                        // [64][136]
    __nv_bfloat16* sB = (__nv_bfloat16*)(dsm + 64 * QG_STRIDE * 2); // [128][136]
    int t = threadIdx.x;
    int v0 = blockIdx.x * 64;            // 313 tiles (tail in last)
    int c0 = blockIdx.y * 128;           // 64 tiles

    // ---- A: h1 tile [64 m x 64 k] -> hi/lo chunks (vectorized) --------------
    #pragma unroll
    for (int q = 0; q < 8; q++) {
        int idx = t + q * 128;           // 1024 float4 groups
        int m = idx >> 4;
        int k4 = (idx & 15) << 2;
        int r = v0 + m;
        float4 va = (r < NN) ? *(const float4*)(g_h1 + (size_t)r * 64 + k4)
                             : make_float4(0.f, 0.f, 0.f, 0.f);
        __nv_bfloat16 h0 = __float2bfloat16(va.x);
        __nv_bfloat16 h1 = __float2bfloat16(va.y);
        __nv_bfloat16 h2 = __float2bfloat16(va.z);
        __nv_bfloat16 h3 = __float2bfloat16(va.w);
        __nv_bfloat16 l0 = __float2bfloat16(va.x - __bfloat162float(h0));
        __nv_bfloat16 l1 = __float2bfloat16(va.y - __bfloat162float(h1));
        __nv_bfloat16 l2 = __float2bfloat16(va.z - __bfloat162float(h2));
        __nv_bfloat16 l3 = __float2bfloat16(va.w - __bfloat162float(h3));
        __nv_bfloat16* row = sA + m * QG_STRIDE;
        uint2 hv; hv.x = pack_bf16(h0, h1); hv.y = pack_bf16(h2, h3);
        uint2 lv; lv.x = pack_bf16(l0, l1); lv.y = pack_bf16(l2, l3);
        *(uint2*)(row + k4)      = hv;
        *(uint2*)(row + 64 + k4) = lv;
    }
    // ---- B: cols c0..c0+127; col C=k2*64+o -> W[k2*4096 + i*64 + o], k=i ----
    int k2b = c0 >> 6;
    #pragma unroll
    for (int j = 0; j < 2; j++) {
        const float* Wb = W + (size_t)(k2b + j) * 4096;
        #pragma unroll
        for (int q = 0; q < 8; q++) {
            int idx = t + q * 128;       // 1024 (o, i4) pairs
            int o = idx & 63;
            int i4 = (idx >> 6) << 2;
            float b0 = Wb[i4 * 64 + o];          // each LDG coalesced over warp
            float b1 = Wb[(i4 + 1) * 64 + o];
            float b2 = Wb[(i4 + 2) * 64 + o];
            float b3 = Wb[(i4 + 3) * 64 + o];
            __nv_bfloat16 h0 = __float2bfloat16(b0);
            __nv_bfloat16 h1 = __float2bfloat16(b1);
            __nv_bfloat16 h2 = __float2bfloat16(b2);
            __nv_bfloat16 h3 = __float2bfloat16(b3);
            __nv_bfloat16 l0 = __float2bfloat16(b0 - __bfloat162float(h0));
            __nv_bfloat16 l1 = __float2bfloat16(b1 - __bfloat162float(h1));
            __nv_bfloat16 l2 = __float2bfloat16(b2 - __bfloat162float(h2));
            __nv_bfloat16 l3 = __float2bfloat16(b3 - __bfloat162float(h3));
            __nv_bfloat16* row = sB + (j * 64 + o) * QG_STRIDE;
            uint2 hv; hv.x = pack_bf16(h0, h1); hv.y = pack_bf16(h2, h3);
            uint2 lv; lv.x = pack_bf16(l0, l1); lv.y = pack_bf16(l2, l3);
            *(uint2*)(row + i4)      = hv;
            *(uint2*)(row + 64 + i4) = lv;
        }
    }
    __syncthreads();

    int warp = t >> 5, lane = t & 31;
    int m0 = (warp & 1) * 32;            // warp tile: 32m x 64n
    int n0 = (warp >> 1) * 64;
    float acc[2][8][4];                  // [fa m16][fb n8][4]
    #pragma unroll
    for (int fa = 0; fa < 2; fa++)
        #pragma unroll
        for (int fb = 0; fb < 8; fb++)
            #pragma unroll
            for (int u = 0; u < 4; u++) acc[fa][fb][u] = 0.f;

    int l7 = lane & 7;
    uint32_t sAu = smem_u32(sA), sBu = smem_u32(sB);
    uint32_t aRowOff = (uint32_t)(m0 + l7 + (((lane >> 3) & 1) << 3));
    uint32_t aColOff = ((lane >> 4) & 1) << 3;
    uint32_t bRowOff = (uint32_t)(n0 + l7 + (((lane >> 4) & 1) << 3));
    uint32_t bColOff = ((lane >> 3) & 1) << 3;

    #pragma unroll 4
    for (int s = 0; s < 12; s++) {
        int aOff = (s & 3) * 16 + ((s >= 4 && s < 8) ? 64 : 0);
        int bOff = (s & 3) * 16 + ((s >= 8) ? 64 : 0);
        uint32_t a[2][4];
        #pragma unroll
        for (int fa = 0; fa < 2; fa++)
            ldsm_x4(a[fa][0], a[fa][1], a[fa][2], a[fa][3],
                    sAu + ((fa * 16 + aRowOff) * QG_STRIDE + aOff + aColOff) * 2);
        #pragma unroll
        for (int nb = 0; nb < 4; nb++) {         // n16 blocks within warp's 64n
            uint32_t b[4];
            ldsm_x4(b[0], b[1], b[2], b[3],
                    sBu + ((nb * 16 + bRowOff) * QG_STRIDE + bOff + bColOff) * 2);
            #pragma unroll
            for (int fa = 0; fa < 2; fa++) {
                mma_bf16(acc[fa][2 * nb],     a[fa], b);
                mma_bf16(acc[fa][2 * nb + 1], a[fa], b + 2);
            }
        }
    }

    // ---- epilogue: frag (m16n8): d0,d1 -> (row, col..col+1), d2,d3 -> row+8 --
    int mr = lane >> 2;
    int cb = c0 + n0 + 2 * (lane & 3);
    #pragma unroll
    for (int fa = 0; fa < 2; fa++) {
        int r0g = v0 + m0 + fa * 16 + mr, r1g = r0g + 8;
        #pragma unroll
        for (int fb = 0; fb < 8; fb++) {
            int c = cb + fb * 8;
            if (r0g < NN) *(float2*)(g_Q + (size_t)r0g * 8192 + c) =
                make_float2(acc[fa][fb][0], acc[fa][fb][1]);
            if (r1g < NN) *(float2*)(g_Q + (size_t)r1g * 8192 + c) =
                make_float2(acc[fa][fb][2], acc[fa][fb][3]);
        }
    }
}

// exclusive scan of outdeg -> rowstart; single block of 1024
__global__ void k_scan() {
    __shared__ int wsum[32];
    __shared__ int carry;
    int t = threadIdx.x, lane = t & 31, wid = t >> 5;
    if (t == 0) carry = 0;
    __syncthreads();
    for (int base = 0; base < NN; base += 1024) {
        int i = base + t;
        int v = (i < NN) ? g_outdeg[i] : 0;
        int incl = v;
        #pragma unroll
        for (int d = 1; d < 32; d <<= 1) {
            int y = __shfl_up_sync(0xffffffffu, incl, d);
            if (lane >= d) incl += y;
        }
        if (lane == 31) wsum[wid] = incl;
        __syncthreads();
        if (wid == 0) {
            int wv = wsum[lane];
            #pragma unroll
            for (int d = 1; d < 32; d <<= 1) {
                int y = __shfl_up_sync(0xffffffffu, wv, d);
                if (lane >= d) wv += y;
            }
            wsum[lane] = wv;
        }
        __syncthreads();
        int pre = ((wid > 0) ? wsum[wid - 1] : 0) + carry;
        if (i < NN) g_rowstart[i] = pre + incl - v;
        __syncthreads();
        if (t == 0) carry += wsum[31];
        __syncthreads();
    }
    if (t == 0) g_rowstart[NN] = carry;
}

__global__ void k_fill(const int* __restrict__ ei) {
    int e = blockIdx.x * blockDim.x + threadIdx.x;
    if (e < NE) {
        int src = ei[e];
        int p = atomicAdd(&g_cursor[src], 1);
        g_ebysrc[g_rowstart[src] + p] = e;
    }
}

// R[v][o] = sum_i h1[v][i] * eb2_2[i*64+o]
__global__ void k_rgemm(const float* __restrict__ eb2) {
    __shared__ float sw[4096];
    int o = threadIdx.x;                 // 64
    for (int j = o; j < 4096; j += 64) sw[j] = eb2[j];
    __syncthreads();
    int v0 = blockIdx.x * 8;             // 2500*8
    for (int n = 0; n < 8; n++) {
        int v = v0 + n;
        float acc = 0.f;
        #pragma unroll 8
        for (int i = 0; i < 64; i++) acc += g_h1[v * 64 + i] * sw[i * 64 + o];
        g_R[v * 64 + o] = acc;
    }
}

// layer2 edge pass: one CTA per src node; Q row in smem; per-edge z2 then msg scatter
__global__ void __launch_bounds__(128) k_l2_edge(const int* __restrict__ ei,
                                                 const float* __restrict__ ea,
                                                 const float* __restrict__ eW1,
                                                 const float* __restrict__ eb1) {
    __shared__ float sQ[8192];
    __shared__ float sR[64];
    __shared__ float sz[128];
    __shared__ float4 sred4[128];
    int v = blockIdx.x;
    int r0 = g_rowstart[v], r1 = g_rowstart[v + 1];
    if (r0 == r1) return;
    int t = threadIdx.x;                 // 128
    const float* Qrow = g_Q + (size_t)v * 8192;
    for (int j = t; j < 2048; j += 128) ((float4*)sQ)[j] = ((const float4*)Qrow)[j];
    if (t < 64) sR[t] = g_R[v * 64 + t];
    float w0 = eW1[t], w1 = eW1[128 + t], w2 = eW1[256 + t], w3 = eW1[384 + t];
    float bz = eb1[t];
    int o4 = (t & 15) * 4, h = t >> 4;
    __syncthreads();
    for (int p = r0; p < r1; p++) {
        int e = g_ebysrc[p];
        int dst = ei[NE + e];
        float a0 = ea[e * 4], a1 = ea[e * 4 + 1], a2 = ea[e * 4 + 2], a3 = ea[e * 4 + 3];
        sz[t] = fmaxf(bz + a0 * w0 + a1 * w1 + a2 * w2 + a3 * w3, 0.f);
        __syncthreads();
        float4 acc = {0, 0, 0, 0};
        int kb = h * 16;
        #pragma unroll
        for (int kk = 0; kk < 16; kk++) {
            float s = sz[kb + kk];
            float4 q = *(const float4*)(sQ + (kb + kk) * 64 + o4);
            acc.x += s * q.x; acc.y += s * q.y; acc.z += s * q.z; acc.w += s * q.w;
        }
        sred4[t] = acc;
        __syncthreads();
        if (t < 16) {
            float4 m = sred4[t];
            #pragma unroll
            for (int hh = 1; hh < 8; hh++) {
                float4 u = sred4[hh * 16 + t];
                m.x += u.x; m.y += u.y; m.z += u.z; m.w += u.w;
            }
            int o = t * 4;
            atomicAdd(&g_agg2[dst * 64 + o],     m.x + sR[o]);
            atomicAdd(&g_agg2[dst * 64 + o + 1], m.y + sR[o + 1]);
            atomicAdd(&g_agg2[dst * 64 + o + 2], m.z + sR[o + 2]);
            atomicAdd(&g_agg2[dst * 64 + o + 3], m.w + sR[o + 3]);
        }
        __syncthreads();
    }
}

// layer2 node + fused LN + pool scatter
__global__ void k_l2_node_ln(const float* __restrict__ root2, const float* __restrict__ bias2,
                             const float* __restrict__ gam, const float* __restrict__ bet,
                             const int* __restrict__ batch) {
    __shared__ float sw[4096];
    __shared__ float sT[8 * 66];
    int o = threadIdx.x;                 // 64
    for (int j = o; j < 4096; j += 64) sw[j] = root2[j];
    __syncthreads();
    int v0 = blockIdx.x * 8;             // 2500*8
    for (int n = 0; n < 8; n++) {
        int v = v0 + n;
        float acc = bias2[o];
        #pragma unroll 8
        for (int i = 0; i < 64; i++) acc += g_h1[v * 64 + i] * sw[i * 64 + o];
        float d = fmaxf((float)g_deg[v], 1.f);
        sT[n * 66 + o] = fmaxf(g_agg2[v * 64 + o] / d + acc, 0.f);
    }
    __syncthreads();
    int lane = o & 31, w = o >> 5;
    float gA = gam[lane], gB = gam[32 + lane];
    float bA = bet[lane], bB = bet[32 + lane];
    for (int j = 0; j < 4; j++) {
        int n = w * 4 + j;
        int v = v0 + n;
        float t0 = sT[n * 66 + lane], t1 = sT[n * 66 + 32 + lane];
        float s = t0 + t1;
        #pragma unroll
        for (int d = 16; d; d >>= 1) s += __shfl_xor_sync(0xffffffffu, s, d);
        float mu = s * (1.f / 64.f);
        float d0 = t0 - mu, d1 = t1 - mu;
        float q = d0 * d0 + d1 * d1;
        #pragma unroll
        for (int d = 16; d; d >>= 1) q += __shfl_xor_sync(0xffffffffu, q, d);
        float rs = rsqrtf(q * (1.f / 64.f) + 1e-5f);
        float y0 = d0 * rs * gA + bA;
        float y1 = d1 * rs * gB + bB;
        int b = batch[v];
        atomicAdd(&g_pool[b * 64 + lane], y0);
        atomicAdd(&g_pool[b * 64 + 32 + lane], y1);
        if (lane == 0) atomicAdd(&g_gcnt[b], 1);
    }
}

__global__ void k_out(float* __restrict__ out) {
    int i = blockIdx.x * blockDim.x + threadIdx.x;
    if (i < NG * 64) {
        float c = fmaxf((float)g_gcnt[i >> 6], 1.f);
        out[i] = g_pool[i] / c;
    }
}

// ---------------- launch ------------------------------------------------------
extern "C" void kernel_launch(void* const* d_in, const int* in_sizes, int n_in,
                              void* d_out, int out_size) {
    const float* x      = (const float*)d_in[0];
    const int*   ei     = (const int*)  d_in[1];
    const float* ea     = (const float*)d_in[2];
    const int*   batch  = (const int*)  d_in[3];
    const float* eW1_1  = (const float*)d_in[4];
    const float* eb1_1  = (const float*)d_in[5];
    const float* eW2_1  = (const float*)d_in[6];
    const float* eb2_1  = (const float*)d_in[7];
    const float* root1  = (const float*)d_in[8];
    const float* bias1  = (const float*)d_in[9];
    const float* g1     = (const float*)d_in[10];
    const float* b1     = (const float*)d_in[11];
    const float* eW1_2  = (const float*)d_in[12];
    const float* eb1_2  = (const float*)d_in[13];
    const float* eW2_2  = (const float*)d_in[14];
    const float* eb2_2  = (const float*)d_in[15];
    const float* root2  = (const float*)d_in[16];
    const float* bias2  = (const float*)d_in[17];
    const float* g2     = (const float*)d_in[18];
    const float* b2     = (const float*)d_in[19];
    float* out = (float*)d_out;

    cudaFuncSetAttribute(k_qgemm_mma, cudaFuncAttributeMaxDynamicSharedMemorySize, QG_SMEM);

    k_zero<<<2048, 256>>>();                                               // 0
    k_l1_edge<<<NE / 4, 256>>>(ei, ea, x, eW1_1, eb1_1);                   // 1
    k_l1_node_ln<<<NN / 16, 64>>>(eW2_1, eb2_1, x, root1, bias1, g1, b1);  // 2
    k_qgemm_mma<<<dim3(313, 64), 128, QG_SMEM>>>(eW2_2);                   // 3 <- ncu window
    k_scan<<<1, 1024>>>();                                                 // 4
    k_fill<<<(NE + 255) / 256, 256>>>(ei);                                 // 5
    k_rgemm<<<NN / 8, 64>>>(eb2_2);                                        // 6
    k_l2_edge<<<NN, 128>>>(ei, ea, eW1_2, eb1_2);                          // 7
    k_l2_node_ln<<<NN / 8, 64>>>(root2, bias2, g2, b2, batch);             // 8
    k_out<<<(NG * 64 + 255) / 256, 256>>>(out);                            // 9
}

// round 17
// speedup vs baseline: 1.7430x; 1.1060x over previous
#include <cuda_runtime.h>
#include <cuda_bf16.h>
#include <cstdint>

#define NN 20000
#define NE 100000
#define NG 64

// ---------------- device scratch (static; no runtime allocation) -------------
__device__ float g_S1[NN * 260];
__device__ float g_h1[NN * 64];
__device__ float g_R[NN * 64];
__device__ float g_Q[163840000];     // [NN][8192]
__device__ float g_agg2[NN * 64];
__device__ int   g_deg[NN];          // in-degree (written by gather)
__device__ int   g_outdeg[NN];
__device__ int   g_indeg[NN];
__device__ int   g_rowstart[NN + 1];   // by src
__device__ int   g_rowstartD[NN + 1];  // by dst
__device__ int   g_cursor[NN];
__device__ int   g_cursorD[NN];
__device__ int   g_ebysrc[NE];
__device__ int   g_ebydst[NE];
__device__ float g_pool[NG * 64];
__device__ int   g_gcnt[NG];

__device__ __forceinline__ uint32_t smem_u32(const void* p) {
    uint32_t a;
    asm("{ .reg .u64 t; cvta.to.shared.u64 t, %1; cvt.u32.u64 %0, t; }" : "=r"(a) : "l"(p));
    return a;
}
__device__ __forceinline__ void ldsm_x4(uint32_t& r0, uint32_t& r1, uint32_t& r2, uint32_t& r3,
                                        uint32_t addr) {
    asm volatile("ldmatrix.sync.aligned.m8n8.x4.shared.b16 {%0,%1,%2,%3}, [%4];"
                 : "=r"(r0), "=r"(r1), "=r"(r2), "=r"(r3) : "r"(addr));
}
__device__ __forceinline__ void mma_bf16(float* d, const uint32_t* a, const uint32_t* b) {
    asm volatile(
        "mma.sync.aligned.m16n8k16.row.col.f32.bf16.bf16.f32 "
        "{%0,%1,%2,%3}, {%4,%5,%6,%7}, {%8,%9}, {%0,%1,%2,%3};"
        : "+f"(d[0]), "+f"(d[1]), "+f"(d[2]), "+f"(d[3])
        : "r"(a[0]), "r"(a[1]), "r"(a[2]), "r"(a[3]), "r"(b[0]), "r"(b[1]));
}
__device__ __forceinline__ uint32_t pack_bf16(__nv_bfloat16 a, __nv_bfloat16 b) {
    __nv_bfloat162 p(a, b);
    return *reinterpret_cast<uint32_t*>(&p);
}

// ---------------- kernels ----------------------------------------------------
__global__ void k_zero() {
    int i = blockIdx.x * blockDim.x + threadIdx.x;
    int st = gridDim.x * blockDim.x;
    for (int j = i; j < NN * 64; j += st) g_agg2[j] = 0.f;
    for (int j = i; j < NG * 64; j += st) g_pool[j] = 0.f;
    for (int j = i; j < NN; j += st) {
        g_outdeg[j] = 0; g_indeg[j] = 0; g_cursor[j] = 0; g_cursorD[j] = 0;
    }
    for (int j = i; j < NG; j += st) g_gcnt[j] = 0;
}

__global__ void k_count(const int* __restrict__ ei) {
    int e = blockIdx.x * blockDim.x + threadIdx.x;
    if (e < NE) {
        atomicAdd(&g_outdeg[ei[e]], 1);
        atomicAdd(&g_indeg[ei[NE + e]], 1);
    }
}

// generic single-block exclusive scan (1024 threads)
__device__ void scan_block(const int* __restrict__ in, int* __restrict__ out) {
    __shared__ int wsum[32];
    __shared__ int carry;
    int t = threadIdx.x, lane = t & 31, wid = t >> 5;
    if (t == 0) carry = 0;
    __syncthreads();
    for (int base = 0; base < NN; base += 1024) {
        int i = base + t;
        int v = (i < NN) ? in[i] : 0;
        int incl = v;
        #pragma unroll
        for (int d = 1; d < 32; d <<= 1) {
            int y = __shfl_up_sync(0xffffffffu, incl, d);
            if (lane >= d) incl += y;
        }
        if (lane == 31) wsum[wid] = incl;
        __syncthreads();
        if (wid == 0) {
            int wv = wsum[lane];
            #pragma unroll
            for (int d = 1; d < 32; d <<= 1) {
                int y = __shfl_up_sync(0xffffffffu, wv, d);
                if (lane >= d) wv += y;
            }
            wsum[lane] = wv;
        }
        __syncthreads();
        int pre = ((wid > 0) ? wsum[wid - 1] : 0) + carry;
        if (i < NN) out[i] = pre + incl - v;
        __syncthreads();
        if (t == 0) carry += wsum[31];
        __syncthreads();
    }
    if (t == 0) out[NN] = carry;
    __syncthreads();
}

__global__ void k_scan2() {
    scan_block(g_outdeg, g_rowstart);
    scan_block(g_indeg, g_rowstartD);
}

__global__ void k_fill2(const int* __restrict__ ei) {
    int e = blockIdx.x * blockDim.x + threadIdx.x;
    if (e < NE) {
        int s = ei[e], d = ei[NE + e];
        int p = atomicAdd(&g_cursor[s], 1);
        g_ebysrc[g_rowstart[s] + p] = e;
        int q = atomicAdd(&g_cursorD[d], 1);
        g_ebydst[g_rowstartD[d] + q] = e;
    }
}

// layer1 gather: CTA per dst node, 64 threads (thread = hidden k).
// acc_i = sum_edges relu(z1_e)[k] * x_src[i]; plus xsum for bias term. No atomics.
__global__ void __launch_bounds__(64) k_l1_gather(const int* __restrict__ ei,
                                                  const float* __restrict__ ea,
                                                  const float* __restrict__ x,
                                                  const float* __restrict__ eW1,
                                                  const float* __restrict__ eb1) {
    int v = blockIdx.x;
    int k = threadIdx.x;
    int r0 = g_rowstartD[v], r1 = g_rowstartD[v + 1];
    float w0 = eW1[k], w1 = eW1[64 + k], w2 = eW1[128 + k], w3 = eW1[192 + k];
    float bz = eb1[k];
    float a0 = 0.f, a1 = 0.f, a2 = 0.f, a3 = 0.f, xsum = 0.f;
    for (int p = r0; p < r1; p++) {
        int e = g_ebydst[p];
        int src = ei[e];
        float4 a = *(const float4*)(ea + 4 * e);
        float4 xs = *(const float4*)(x + 4 * src);
        float z = fmaxf(bz + a.x * w0 + a.y * w1 + a.z * w2 + a.w * w3, 0.f);
        a0 += z * xs.x; a1 += z * xs.y; a2 += z * xs.z; a3 += z * xs.w;
        if (k < 4) xsum += (k == 0) ? xs.x : (k == 1) ? xs.y : (k == 2) ? xs.z : xs.w;
    }
    float* S = g_S1 + v * 260;
    *(float4*)(S + k * 4) = make_float4(a0, a1, a2, a3);
    if (k < 4) S[256 + k] = xsum;
    if (k == 0) g_deg[v] = r1 - r0;
}

// layer1 node + fused layernorm -> g_h1
__global__ void k_l1_node_ln(const float* __restrict__ eW2, const float* __restrict__ eb2,
                             const float* __restrict__ x, const float* __restrict__ root1,
                             const float* __restrict__ bias1,
                             const float* __restrict__ gam, const float* __restrict__ bet) {
    __shared__ float sS[16 * 260];
    __shared__ float sT[16 * 66];
    int o = threadIdx.x;                 // 64
    int v0 = blockIdx.x * 16;            // 1250*16 = 20000
    for (int l = o; l < 16 * 260; l += 64) sS[l] = g_S1[v0 * 260 + l];
    __syncthreads();
    float acc[16];
    #pragma unroll
    for (int n = 0; n < 16; n++) acc[n] = 0.f;
    for (int k = 0; k < 64; k++) {
        #pragma unroll
        for (int i = 0; i < 4; i++) {
            float w = eW2[k * 256 + i * 64 + o];
            #pragma unroll
            for (int n = 0; n < 16; n++) acc[n] += sS[n * 260 + k * 4 + i] * w;
        }
    }
    #pragma unroll
    for (int i = 0; i < 4; i++) {
        float w = eb2[i * 64 + o];
        #pragma unroll
        for (int n = 0; n < 16; n++) acc[n] += sS[n * 260 + 256 + i] * w;
    }
    for (int n = 0; n < 16; n++) {
        int v = v0 + n;
        float d = fmaxf((float)g_deg[v], 1.f);
        float r = bias1[o];
        #pragma unroll
        for (int i = 0; i < 4; i++) r += x[v * 4 + i] * root1[i * 64 + o];
        sT[n * 66 + o] = fmaxf(acc[n] / d + r, 0.f);
    }
    __syncthreads();
    int lane = o & 31, w = o >> 5;
    float gA = gam[lane], gB = gam[32 + lane];
    float bA = bet[lane], bB = bet[32 + lane];
    for (int j = 0; j < 8; j++) {
        int n = w * 8 + j;
        int v = v0 + n;
        float t0 = sT[n * 66 + lane], t1 = sT[n * 66 + 32 + lane];
        float s = t0 + t1;
        #pragma unroll
        for (int d = 16; d; d >>= 1) s += __shfl_xor_sync(0xffffffffu, s, d);
        float mu = s * (1.f / 64.f);
        float d0 = t0 - mu, d1 = t1 - mu;
        float q = d0 * d0 + d1 * d1;
        #pragma unroll
        for (int d = 16; d; d >>= 1) q += __shfl_xor_sync(0xffffffffu, q, d);
        float rs = rsqrtf(q * (1.f / 64.f) + 1e-5f);
        g_h1[v * 64 + lane]      = d0 * rs * gA + bA;
        g_h1[v * 64 + 32 + lane] = d1 * rs * gB + bB;
    }
}

// ---------------- mma.sync Q-GEMM (unchanged from R14 win) --------------------
#define QG_STRIDE 136
#define QG_SMEM ((64 + 128) * QG_STRIDE * 2)    // 52224 B

__global__ void __launch_bounds__(128, 4) k_qgemm_mma(const float* __restrict__ W) {
    extern __shared__ __align__(16) char dsm[];
    __nv_bfloat16* sA = (__nv_bfloat16*)dsm;                        // [64][136]
    __nv_bfloat16* sB = (__nv_bfloat16*)(dsm + 64 * QG_STRIDE * 2); // [128][136]
    int t = threadIdx.x;
    int v0 = blockIdx.x * 64;
    int c0 = blockIdx.y * 128;

    #pragma unroll
    for (int q = 0; q < 8; q++) {
        int idx = t + q * 128;
        int m = idx >> 4;
        int k4 = (idx & 15) << 2;
        int r = v0 + m;
        float4 va = (r < NN) ? *(const float4*)(g_h1 + (size_t)r * 64 + k4)
                             : make_float4(0.f, 0.f, 0.f, 0.f);
        __nv_bfloat16 h0 = __float2bfloat16(va.x);
        __nv_bfloat16 h1 = __float2bfloat16(va.y);
        __nv_bfloat16 h2 = __float2bfloat16(va.z);
        __nv_bfloat16 h3 = __float2bfloat16(va.w);
        __nv_bfloat16 l0 = __float2bfloat16(va.x - __bfloat162float(h0));
        __nv_bfloat16 l1 = __float2bfloat16(va.y - __bfloat162float(h1));
        __nv_bfloat16 l2 = __float2bfloat16(va.z - __bfloat162float(h2));
        __nv_bfloat16 l3 = __float2bfloat16(va.w - __bfloat162float(h3));
        __nv_bfloat16* row = sA + m * QG_STRIDE;
        uint2 hv; hv.x = pack_bf16(h0, h1); hv.y = pack_bf16(h2, h3);
        uint2 lv; lv.x = pack_bf16(l0, l1); lv.y = pack_bf16(l2, l3);
        *(uint2*)(row + k4)      = hv;
        *(uint2*)(row + 64 + k4) = lv;
    }
    int k2b = c0 >> 6;
    #pragma unroll
    for (int j = 0; j < 2; j++) {
        const float* Wb = W + (size_t)(k2b + j) * 4096;
        #pragma unroll
        for (int q = 0; q < 8; q++) {
            int idx = t + q * 128;
            int o = idx & 63;
            int i4 = (idx >> 6) << 2;
            float b0 = Wb[i4 * 64 + o];
            float b1 = Wb[(i4 + 1) * 64 + o];
            float b2 = Wb[(i4 + 2) * 64 + o];
            float b3 = Wb[(i4 + 3) * 64 + o];
            __nv_bfloat16 h0 = __float2bfloat16(b0);
            __nv_bfloat16 h1 = __float2bfloat16(b1);
            __nv_bfloat16 h2 = __float2bfloat16(b2);
            __nv_bfloat16 h3 = __float2bfloat16(b3);
            __nv_bfloat16 l0 = __float2bfloat16(b0 - __bfloat162float(h0));
            __nv_bfloat16 l1 = __float2bfloat16(b1 - __bfloat162float(h1));
            __nv_bfloat16 l2 = __float2bfloat16(b2 - __bfloat162float(h2));
            __nv_bfloat16 l3 = __float2bfloat16(b3 - __bfloat162float(h3));
            __nv_bfloat16* row = sB + (j * 64 + o) * QG_STRIDE;
            uint2 hv; hv.x = pack_bf16(h0, h1); hv.y = pack_bf16(h2, h3);
            uint2 lv; lv.x = pack_bf16(l0, l1); lv.y = pack_bf16(l2, l3);
            *(uint2*)(row + i4)      = hv;
            *(uint2*)(row + 64 + i4) = lv;
        }
    }
    __syncthreads();

    int warp = t >> 5, lane = t & 31;
    int m0 = (warp & 1) * 32;
    int n0 = (warp >> 1) * 64;
    float acc[2][8][4];
    #pragma unroll
    for (int fa = 0; fa < 2; fa++)
        #pragma unroll
        for (int fb = 0; fb < 8; fb++)
            #pragma unroll
            for (int u = 0; u < 4; u++) acc[fa][fb][u] = 0.f;

    int l7 = lane & 7;
    uint32_t sAu = smem_u32(sA), sBu = smem_u32(sB);
    uint32_t aRowOff = (uint32_t)(m0 + l7 + (((lane >> 3) & 1) << 3));
    uint32_t aColOff = ((lane >> 4) & 1) << 3;
    uint32_t bRowOff = (uint32_t)(n0 + l7 + (((lane >> 4) & 1) << 3));
    uint32_t bColOff = ((lane >> 3) & 1) << 3;

    #pragma unroll 4
    for (int s = 0; s < 12; s++) {
        int aOff = (s & 3) * 16 + ((s >= 4 && s < 8) ? 64 : 0);
        int bOff = (s & 3) * 16 + ((s >= 8) ? 64 : 0);
        uint32_t a[2][4];
        #pragma unroll
        for (int fa = 0; fa < 2; fa++)
            ldsm_x4(a[fa][0], a[fa][1], a[fa][2], a[fa][3],
                    sAu + ((fa * 16 + aRowOff) * QG_STRIDE + aOff + aColOff) * 2);
        #pragma unroll
        for (int nb = 0; nb < 4; nb++) {
            uint32_t b[4];
            ldsm_x4(b[0], b[1], b[2], b[3],
                    sBu + ((nb * 16 + bRowOff) * QG_STRIDE + bOff + bColOff) * 2);
            #pragma unroll
            for (int fa = 0; fa < 2; fa++) {
                mma_bf16(acc[fa][2 * nb],     a[fa], b);
                mma_bf16(acc[fa][2 * nb + 1], a[fa], b + 2);
            }
        }
    }

    int mr = lane >> 2;
    int cb = c0 + n0 + 2 * (lane & 3);
    #pragma unroll
    for (int fa = 0; fa < 2; fa++) {
        int r0g = v0 + m0 + fa * 16 + mr, r1g = r0g + 8;
        #pragma unroll
        for (int fb = 0; fb < 8; fb++) {
            int c = cb + fb * 8;
            if (r0g < NN) *(float2*)(g_Q + (size_t)r0g * 8192 + c) =
                make_float2(acc[fa][fb][0], acc[fa][fb][1]);
            if (r1g < NN) *(float2*)(g_Q + (size_t)r1g * 8192 + c) =
                make_float2(acc[fa][fb][2], acc[fa][fb][3]);
        }
    }
}

// R[v][o] = sum_i h1[v][i] * eb2_2[i*64+o]
__global__ void k_rgemm(const float* __restrict__ eb2) {
    __shared__ float sw[4096];
    int o = threadIdx.x;                 // 64
    for (int j = o; j < 4096; j += 64) sw[j] = eb2[j];
    __syncthreads();
    int v0 = blockIdx.x * 8;             // 2500*8
    for (int n = 0; n < 8; n++) {
        int v = v0 + n;
        float acc = 0.f;
        #pragma unroll 8
        for (int i = 0; i < 64; i++) acc += g_h1[v * 64 + i] * sw[i * 64 + o];
        g_R[v * 64 + o] = acc;
    }
}

// layer2 edge pass v2: one CTA per src node; warp-per-edge (2 edges batched per
// warp pass), no CTA barriers in the loop. Lane owns 2 output cols (o=2*lane).
__global__ void __launch_bounds__(128) k_l2_edge(const int* __restrict__ ei,
                                                 const float* __restrict__ ea,
                                                 const float* __restrict__ eW1,
                                                 const float* __restrict__ eb1) {
    __shared__ float sQ[8192];
    __shared__ float sR[64];
    __shared__ float sz[4][2][128];
    int v = blockIdx.x;
    int r0 = g_rowstart[v], r1 = g_rowstart[v + 1];
    if (r0 == r1) return;
    int t = threadIdx.x, w = t >> 5, lane = t & 31;
    const float* Qrow = g_Q + (size_t)v * 8192;
    for (int j = t; j < 2048; j += 128) ((float4*)sQ)[j] = ((const float4*)Qrow)[j];
    if (t < 64) sR[t] = g_R[v * 64 + t];
    // per-lane z weights for k = lane*4 + j  (eW1_2 layout: [4][128])
    int kb = lane * 4;
    float zw0[4], zw1[4], zw2[4], zw3[4], zb[4];
    #pragma unroll
    for (int j = 0; j < 4; j++) {
        zw0[j] = eW1[kb + j];       zw1[j] = eW1[128 + kb + j];
        zw2[j] = eW1[256 + kb + j]; zw3[j] = eW1[384 + kb + j];
        zb[j]  = eb1[kb + j];
    }
    __syncthreads();
    int o = 2 * lane;
    float R0 = sR[o], R1 = sR[o + 1];
    for (int p = r0 + 2 * w; p < r1; p += 8) {
        int e0 = g_ebysrc[p];
        bool two = (p + 1 < r1);
        int e1 = two ? g_ebysrc[p + 1] : e0;
        int d0 = ei[NE + e0], d1 = ei[NE + e1];
        float4 a0 = *(const float4*)(ea + 4 * e0);
        float4 a1 = *(const float4*)(ea + 4 * e1);
        #pragma unroll
        for (int j = 0; j < 4; j++) {
            sz[w][0][kb + j] = fmaxf(zb[j] + a0.x * zw0[j] + a0.y * zw1[j]
                                           + a0.z * zw2[j] + a0.w * zw3[j], 0.f);
            sz[w][1][kb + j] = fmaxf(zb[j] + a1.x * zw0[j] + a1.y * zw1[j]
                                           + a1.z * zw2[j] + a1.w * zw3[j], 0.f);
        }
        __syncwarp();
        float2 m0 = make_float2(0.f, 0.f), m1 = make_float2(0.f, 0.f);
        #pragma unroll 8
        for (int k = 0; k < 128; k++) {
            float2 q = *(const float2*)(sQ + k * 64 + o);
            float z0 = sz[w][0][k], z1 = sz[w][1][k];
            m0.x += z0 * q.x; m0.y += z0 * q.y;
            m1.x += z1 * q.x; m1.y += z1 * q.y;
        }
        atomicAdd(&g_agg2[d0 * 64 + o],     m0.x + R0);
        atomicAdd(&g_agg2[d0 * 64 + o + 1], m0.y + R1);
        if (two) {
            atomicAdd(&g_agg2[d1 * 64 + o],     m1.x + R0);
            atomicAdd(&g_agg2[d1 * 64 + o + 1], m1.y + R1);
        }
        __syncwarp();
    }
}

// layer2 node + fused LN + pool scatter
__global__ void k_l2_node_ln(const float* __restrict__ root2, const float* __restrict__ bias2,
                             const float* __restrict__ gam, const float* __restrict__ bet,
                             const int* __restrict__ batch) {
    __shared__ float sw[4096];
    __shared__ float sT[8 * 66];
    int o = threadIdx.x;                 // 64
    for (int j = o; j < 4096; j += 64) sw[j] = root2[j];
    __syncthreads();
    int v0 = blockIdx.x * 8;             // 2500*8
    for (int n = 0; n < 8; n++) {
        int v = v0 + n;
        float acc = bias2[o];
        #pragma unroll 8
        for (int i = 0; i < 64; i++) acc += g_h1[v * 64 + i] * sw[i * 64 + o];
        float d = fmaxf((float)g_deg[v], 1.f);
        sT[n * 66 + o] = fmaxf(g_agg2[v * 64 + o] / d + acc, 0.f);
    }
    __syncthreads();
    int lane = o & 31, w = o >> 5;
    float gA = gam[lane], gB = gam[32 + lane];
    float bA = bet[lane], bB = bet[32 + lane];
    for (int j = 0; j < 4; j++) {
        int n = w * 4 + j;
        int v = v0 + n;
        float t0 = sT[n * 66 + lane], t1 = sT[n * 66 + 32 + lane];
        float s = t0 + t1;
        #pragma unroll
        for (int d = 16; d; d >>= 1) s += __shfl_xor_sync(0xffffffffu, s, d);
        float mu = s * (1.f / 64.f);
        float d0 = t0 - mu, d1 = t1 - mu;
        float q = d0 * d0 + d1 * d1;
        #pragma unroll
        for (int d = 16; d; d >>= 1) q += __shfl_xor_sync(0xffffffffu, q, d);
        float rs = rsqrtf(q * (1.f / 64.f) + 1e-5f);
        float y0 = d0 * rs * gA + bA;
        float y1 = d1 * rs * gB + bB;
        int b = batch[v];
        atomicAdd(&g_pool[b * 64 + lane], y0);
        atomicAdd(&g_pool[b * 64 + 32 + lane], y1);
        if (lane == 0) atomicAdd(&g_gcnt[b], 1);
    }
}

__global__ void k_out(float* __restrict__ out) {
    int i = blockIdx.x * blockDim.x + threadIdx.x;
    if (i < NG * 64) {
        float c = fmaxf((float)g_gcnt[i >> 6], 1.f);
        out[i] = g_pool[i] / c;
    }
}

// ---------------- launch ------------------------------------------------------
extern "C" void kernel_launch(void* const* d_in, const int* in_sizes, int n_in,
                              void* d_out, int out_size) {
    const float* x      = (const float*)d_in[0];
    const int*   ei     = (const int*)  d_in[1];
    const float* ea     = (const float*)d_in[2];
    const int*   batch  = (const int*)  d_in[3];
    const float* eW1_1  = (const float*)d_in[4];
    const float* eb1_1  = (const float*)d_in[5];
    const float* eW2_1  = (const float*)d_in[6];
    const float* eb2_1  = (const float*)d_in[7];
    const float* root1  = (const float*)d_in[8];
    const float* bias1  = (const float*)d_in[9];
    const float* g1     = (const float*)d_in[10];
    const float* b1     = (const float*)d_in[11];
    const float* eW1_2  = (const float*)d_in[12];
    const float* eb1_2  = (const float*)d_in[13];
    const float* eW2_2  = (const float*)d_in[14];
    const float* eb2_2  = (const float*)d_in[15];
    const float* root2  = (const float*)d_in[16];
    const float* bias2  = (const float*)d_in[17];
    const float* g2     = (const float*)d_in[18];
    const float* b2     = (const float*)d_in[19];
    float* out = (float*)d_out;

    cudaFuncSetAttribute(k_qgemm_mma, cudaFuncAttributeMaxDynamicSharedMemorySize, QG_SMEM);

    k_zero<<<1024, 256>>>();                                               // 0
    k_count<<<(NE + 255) / 256, 256>>>(ei);                                // 1
    k_scan2<<<1, 1024>>>();                                                // 2
    k_fill2<<<(NE + 255) / 256, 256>>>(ei);                                // 3
    k_l1_gather<<<NN, 64>>>(ei, ea, x, eW1_1, eb1_1);                      // 4
    k_l1_node_ln<<<NN / 16, 64>>>(eW2_1, eb2_1, x, root1, bias1, g1, b1);  // 5
    k_qgemm_mma<<<dim3(313, 64), 128, QG_SMEM>>>(eW2_2);                   // 6
    k_rgemm<<<NN / 8, 64>>>(eb2_2);                                        // 7
    k_l2_edge<<<NN, 128>>>(ei, ea, eW1_2, eb1_2);                          // 8
    k_l2_node_ln<<<NN / 8, 64>>>(root2, bias2, g2, b2, batch);             // 9
    k_out<<<(NG * 64 + 255) / 256, 256>>>(out);                            // 10
}